// round 15
// baseline (speedup 1.0000x reference)
#include <cuda_runtime.h>
#include <cuda.h>
#include <cuda_bf16.h>
#include <math.h>
#include <stdint.h>

#define T_TOK 2048
#define H_DIM 2048
#define I_DIM 768
#define E_NUM 32
#define K_TOP 8
#define CAP   1024
#define A_TOTAL (T_TOK * K_TOP)
#define N1 (2 * I_DIM)          // 1536

#define TPE1 24                 // gemm1: 4 mpair x 6 nblk (128 h cols per tile)
#define TPE2 32                 // gemm2: 4 mpair x 8 nblk (256 H cols per tile)
#define NTIL1 (E_NUM * TPE1)    // 768
#define NTIL2 (E_NUM * TPE2)    // 1024
#define NCLUS 74
#define NSTG  3

#if defined(__CUDA_ARCH__)
#  if defined(__CUDA_ARCH_FEAT_SM103_ALL) || defined(__CUDA_ARCH_FEAT_SM100_ALL) || \
      (defined(__CUDA_ARCH_SPECIFIC__) && (__CUDA_ARCH_SPECIFIC__ == 1030 || __CUDA_ARCH_SPECIFIC__ == 1000))
#    define HAS_TCGEN05 1
#  else
#    define HAS_TCGEN05 0
#  endif
#else
#  define HAS_TCGEN05 0
#endif

// ---------------- device scratch ----------------
__device__ float g_gate_wT[E_NUM * H_DIM];
__device__ int   g_cnt[E_NUM];
__device__ int   g_tok[E_NUM * CAP];
__device__ int   g_aid[E_NUM * CAP];
__device__ float g_wgt[E_NUM * CAP];
__device__ unsigned short g_gah[(size_t)E_NUM * CAP * H_DIM];  // pregathered A hi
__device__ unsigned short g_gal[(size_t)E_NUM * CAP * H_DIM];  // pregathered A lo
__device__ unsigned short g_hh[(size_t)E_NUM * CAP * I_DIM];
__device__ unsigned short g_hl[(size_t)E_NUM * CAP * I_DIM];
__device__ float g_y[(size_t)A_TOTAL * H_DIM];
__device__ unsigned short g_w1h[(size_t)E_NUM * N1 * H_DIM];
__device__ unsigned short g_w1l[(size_t)E_NUM * N1 * H_DIM];
__device__ unsigned short g_w2h[(size_t)E_NUM * H_DIM * I_DIM];
__device__ unsigned short g_w2l[(size_t)E_NUM * H_DIM * I_DIM];

// ---------------- helpers ----------------
__device__ __forceinline__ void split_bf16(float x, unsigned short& h, unsigned short& l) {
    __nv_bfloat16 bh = __float2bfloat16_rn(x);
    h = *reinterpret_cast<unsigned short*>(&bh);
    float r = x - __bfloat162float(bh);
    __nv_bfloat16 bl = __float2bfloat16_rn(r);
    l = *reinterpret_cast<unsigned short*>(&bl);
}
__device__ __forceinline__ uint32_t smem_u32(const void* p) {
    return (uint32_t)__cvta_generic_to_shared(p);
}

// ---------------- weight conversion (64-row tiles); w1 pass also preps router state ----------------
template<int KD, int ND>
__global__ __launch_bounds__(256) void conv_kernel(const float* __restrict__ W,
                                                   unsigned short* __restrict__ Wh,
                                                   unsigned short* __restrict__ Wl,
                                                   const float* __restrict__ gate_w) {
    const int e = blockIdx.z;
    const int k0 = blockIdx.x * 64;
    const int n0 = blockIdx.y * 64;
    __shared__ float ts[64][65];
    const int tid = threadIdx.x;

    if (gate_w && blockIdx.x == 0 && blockIdx.y == 0) {
        for (int h = tid; h < H_DIM; h += 256)
            g_gate_wT[e * H_DIM + h] = gate_w[h * E_NUM + e];
        if (e == 0 && tid < E_NUM) g_cnt[tid] = 0;
    }

    const int lr = tid >> 4, lc = (tid & 15) * 4;
    const float* src = W + (size_t)e * KD * ND + (size_t)k0 * ND + n0;
#pragma unroll
    for (int it = 0; it < 4; it++) {
        const int row = lr + it * 16;
        float4 v = *(const float4*)(src + (size_t)row * ND + lc);
        ts[row][lc + 0] = v.x; ts[row][lc + 1] = v.y;
        ts[row][lc + 2] = v.z; ts[row][lc + 3] = v.w;
    }
    __syncthreads();

    const int n = tid >> 2, ks = (tid & 3) * 16;
    uint32_t hh[8], ll[8];
#pragma unroll
    for (int q = 0; q < 8; q++) {
        unsigned short h0, h1, l0, l1;
        split_bf16(ts[ks + 2 * q][n],     h0, l0);
        split_bf16(ts[ks + 2 * q + 1][n], h1, l1);
        hh[q] = (uint32_t)h0 | ((uint32_t)h1 << 16);
        ll[q] = (uint32_t)l0 | ((uint32_t)l1 << 16);
    }
    const size_t doff = ((size_t)e * ND + n0 + n) * KD + k0 + ks;
    *(uint4*)(Wh + doff)     = make_uint4(hh[0], hh[1], hh[2], hh[3]);
    *(uint4*)(Wh + doff + 8) = make_uint4(hh[4], hh[5], hh[6], hh[7]);
    *(uint4*)(Wl + doff)     = make_uint4(ll[0], ll[1], ll[2], ll[3]);
    *(uint4*)(Wl + doff + 8) = make_uint4(ll[4], ll[5], ll[6], ll[7]);
}

// ---------------- router ----------------
__global__ __launch_bounds__(256) void router_kernel(const float* __restrict__ x,
                                                     const float* __restrict__ gate_b) {
    __shared__ float xs[H_DIM];
    __shared__ float lg[E_NUM];
    const int t = blockIdx.x;
    const int tid = threadIdx.x;

    const float4* xr = (const float4*)(x + (size_t)t * H_DIM);
    for (int i = tid; i < H_DIM / 4; i += 256) ((float4*)xs)[i] = xr[i];
    __syncthreads();

    const int w = tid >> 5, lane = tid & 31;
#pragma unroll
    for (int ee = 0; ee < 4; ee++) {
        const int e = (w << 2) + ee;
        const float* gw = g_gate_wT + (size_t)e * H_DIM;
        float s = 0.f;
        for (int h = lane; h < H_DIM; h += 32) s += xs[h] * gw[h];
#pragma unroll
        for (int off = 16; off; off >>= 1) s += __shfl_xor_sync(0xffffffffu, s, off);
        if (lane == 0) lg[e] = s + gate_b[e];
    }
    __syncthreads();

    if (tid == 0) {
        float mx = lg[0];
#pragma unroll
        for (int e = 1; e < E_NUM; e++) mx = fmaxf(mx, lg[e]);
        float p[E_NUM];
#pragma unroll
        for (int e = 0; e < E_NUM; e++) p[e] = __expf(lg[e] - mx);
        float vals[K_TOP]; int sel[K_TOP]; float vsum = 0.f;
#pragma unroll
        for (int k = 0; k < K_TOP; k++) {
            int bj = 0; float bv = p[0];
            for (int e = 1; e < E_NUM; e++) if (p[e] > bv) { bv = p[e]; bj = e; }
            sel[k] = bj; vals[k] = bv; vsum += bv; p[bj] = -1.f;
        }
        const float inv = 1.f / vsum;
#pragma unroll
        for (int k = 0; k < K_TOP; k++) {
            const int e = sel[k];
            int slot = atomicAdd(&g_cnt[e], 1);
            if (slot < CAP) {
                g_tok[e * CAP + slot] = t;
                g_aid[e * CAP + slot] = (t << 3) + k;
                g_wgt[e * CAP + slot] = vals[k] * inv;
            }
        }
    }
}

// ---------------- pregather: x rows -> split bf16 hi/lo [E*CAP][H] ----------------
__global__ __launch_bounds__(256) void pregather_kernel(const float* __restrict__ x) {
    const int bid = blockIdx.x;                // e*CAP + slot
    const int e = bid >> 10, slot = bid & (CAP - 1);
    const int count = g_cnt[e];
    int s = slot; if (s >= count) s = (count > 0) ? count - 1 : 0;
    const int tok = g_tok[e * CAP + s];
    const int c0 = threadIdx.x * 8;
    const float* src = x + (size_t)tok * H_DIM + c0;
    float4 v0 = *(const float4*)src;
    float4 v1 = *(const float4*)(src + 4);
    float vv[8] = {v0.x, v0.y, v0.z, v0.w, v1.x, v1.y, v1.z, v1.w};
    uint32_t hh[4], ll[4];
#pragma unroll
    for (int q = 0; q < 4; q++) {
        unsigned short h0, h1, l0, l1;
        split_bf16(vv[2 * q],     h0, l0);
        split_bf16(vv[2 * q + 1], h1, l1);
        hh[q] = (uint32_t)h0 | ((uint32_t)h1 << 16);
        ll[q] = (uint32_t)l0 | ((uint32_t)l1 << 16);
    }
    const size_t o = (size_t)bid * H_DIM + c0;
    *(uint4*)(g_gah + o) = make_uint4(hh[0], hh[1], hh[2], hh[3]);
    *(uint4*)(g_gal + o) = make_uint4(ll[0], ll[1], ll[2], ll[3]);
}

// ---------------- smem arena: 3 stages x 64KB ----------------
#define SM_TMEMPTR 0
#define SM_FILL    16          // FILL[s]@16+8s (count=1 + expect_tx, on rank0)
#define SM_DONE    48          // DONE[s]@48+8s (count=1, commit multicast)
#define SM_TDONE   80          // TDONE[b]@80+8b (count=1, commit multicast)
#define SM_EPI     96          // EPI[b]@96+8b (count=16, on rank0)
#define SM_BUF     1024
#define OFF_AH     0           // 16KB (128 rows x 128B)
#define OFF_AL     16384
#define OFF_BH     32768       // 16KB (128 local rows x 128B)
#define OFF_BL     49152
#define STG_SZ     65536
#define SMEM_TC    (SM_BUF + NSTG * STG_SZ)   // 197632
#define CHUNK_TX   131072      // 64KB x 2 CTAs

#if HAS_TCGEN05
__device__ __forceinline__ uint32_t ctarank() {
    uint32_t r;
    asm("mov.u32 %0, %%cluster_ctarank;" : "=r"(r));
    return r;
}
__device__ __forceinline__ uint64_t desc_k_sw128(uint32_t addr) {
    return ((uint64_t)(addr >> 4) & 0x3FFF) | (1ull << 16) | (64ull << 32)
         | (1ull << 46) | (2ull << 61);
}
// idesc kind::f16 cg2: dtype=F32, atype=BF16, btype=BF16, N=256, M=256 (validated)
#define MMA_IDESC2 ((1u << 4) | (1u << 7) | (1u << 10) | ((256u / 8) << 17) | ((256u / 16) << 24))

__device__ __forceinline__ void tcg_mma2(uint32_t d, uint64_t a, uint64_t b, uint32_t en) {
    asm volatile(
        "{\n\t.reg .pred p;\n\tsetp.ne.u32 p, %4, 0;\n\t"
        "tcgen05.mma.cta_group::2.kind::f16 [%0], %1, %2, %3, "
        "{%5, %5, %5, %5, %5, %5, %5, %5}, p;\n\t}"
        :: "r"(d), "l"(a), "l"(b), "r"(MMA_IDESC2), "r"(en), "r"(0u) : "memory");
}
__device__ __forceinline__ void tcg_commit_mc2(uint32_t mbar, uint16_t mask) {
    asm volatile(
        "tcgen05.commit.cta_group::2.mbarrier::arrive::one.shared::cluster.multicast::cluster.b64 [%0], %1;"
        :: "r"(mbar), "h"(mask) : "memory");
}
__device__ __forceinline__ void tcg_alloc2(uint32_t smem_res, uint32_t ncols) {
    asm volatile("tcgen05.alloc.cta_group::2.sync.aligned.shared::cta.b32 [%0], %1;"
                 :: "r"(smem_res), "r"(ncols) : "memory");
}
__device__ __forceinline__ void tcg_dealloc2(uint32_t tmem, uint32_t ncols) {
    asm volatile("tcgen05.dealloc.cta_group::2.sync.aligned.b32 %0, %1;" :: "r"(tmem), "r"(ncols));
}
__device__ __forceinline__ void tcg_relinq2() {
    asm volatile("tcgen05.relinquish_alloc_permit.cta_group::2.sync.aligned;");
}
__device__ __forceinline__ void mbar_init(uint32_t mbar, uint32_t cnt) {
    asm volatile("mbarrier.init.shared.b64 [%0], %1;" :: "r"(mbar), "r"(cnt) : "memory");
}
__device__ __forceinline__ void mbar_expect_tx(uint32_t mbar, uint32_t bytes) {
    asm volatile("mbarrier.arrive.expect_tx.shared.b64 _, [%0], %1;"
                 :: "r"(mbar), "r"(bytes) : "memory");
}
__device__ __forceinline__ void mbar_arrive_rank0(uint32_t addr) {
    asm volatile(
        "{\n\t.reg .b32 r;\n\t"
        "mapa.shared::cluster.u32 r, %0, 0;\n\t"
        "mbarrier.arrive.shared::cluster.b64 _, [r];\n\t}"
        :: "r"(addr) : "memory");
}
__device__ __forceinline__ void mbar_wait(uint32_t mbar, uint32_t parity) {
    uint32_t done;
    asm volatile(
        "{\n\t.reg .pred p;\n\t"
        "mbarrier.try_wait.parity.acquire.cta.shared::cta.b64 p, [%1], %2;\n\t"
        "selp.b32 %0, 1, 0, p;\n\t}"
        : "=r"(done) : "r"(mbar), "r"(parity) : "memory");
    if (!done) {
        asm volatile(
            "{\n\t.reg .pred P1;\n\t"
            "WAIT_LOOP_%=:\n\t"
            "mbarrier.try_wait.parity.acquire.cta.shared::cta.b64 P1, [%0], %1, 0x989680;\n\t"
            "@P1 bra.uni WAIT_DONE_%=;\n\t"
            "bra.uni WAIT_LOOP_%=;\n\t"
            "WAIT_DONE_%=:\n\t}"
            :: "r"(mbar), "r"(parity) : "memory");
    }
}
// cg2 TMA: both CTAs issue; complete_tx credited to rank0's barrier (bit 24 cleared)
__device__ __forceinline__ void tma_cg2(uint32_t dst, const CUtensorMap* map,
                                        int x, int y, uint32_t bar) {
    asm volatile(
        "{\n\t.reg .b32 lb;\n\tand.b32 lb, %5, 0xFEFFFFFF;\n\t"
        "cp.async.bulk.tensor.3d.cta_group::2.shared::cluster.global.tile.mbarrier::complete_tx::bytes "
        "[%0], [%1, {%2, %3, %4}], [lb];\n\t}"
        :: "r"(dst), "l"(map), "r"(x), "r"(y), "r"(0), "r"(bar) : "memory");
}
__device__ __forceinline__ void tcg_fence_after() {
    asm volatile("tcgen05.fence::after_thread_sync;" ::: "memory");
}
__device__ __forceinline__ void tcg_fence_before() {
    asm volatile("tcgen05.fence::before_thread_sync;" ::: "memory");
}
__device__ __forceinline__ void tcg_wait_ld() {
    asm volatile("tcgen05.wait::ld.sync.aligned;" ::: "memory");
}
__device__ __forceinline__ void cluster_sync_() {
    asm volatile("barrier.cluster.arrive.aligned;" ::: "memory");
    asm volatile("barrier.cluster.wait.aligned;" ::: "memory");
}
__device__ __forceinline__ void ldtm32(uint32_t* r, uint32_t addr) {
    asm volatile(
        "tcgen05.ld.sync.aligned.32x32b.x32.b32 "
        "{%0, %1, %2, %3, %4, %5, %6, %7, "
        " %8, %9, %10, %11, %12, %13, %14, %15, "
        " %16, %17, %18, %19, %20, %21, %22, %23, "
        " %24, %25, %26, %27, %28, %29, %30, %31}, [%32];"
        : "=r"(r[0]),  "=r"(r[1]),  "=r"(r[2]),  "=r"(r[3]),
          "=r"(r[4]),  "=r"(r[5]),  "=r"(r[6]),  "=r"(r[7]),
          "=r"(r[8]),  "=r"(r[9]),  "=r"(r[10]), "=r"(r[11]),
          "=r"(r[12]), "=r"(r[13]), "=r"(r[14]), "=r"(r[15]),
          "=r"(r[16]), "=r"(r[17]), "=r"(r[18]), "=r"(r[19]),
          "=r"(r[20]), "=r"(r[21]), "=r"(r[22]), "=r"(r[23]),
          "=r"(r[24]), "=r"(r[25]), "=r"(r[26]), "=r"(r[27]),
          "=r"(r[28]), "=r"(r[29]), "=r"(r[30]), "=r"(r[31])
        : "r"(addr));
}
#endif  // HAS_TCGEN05

// Persistent 2-CTA TMA+tcgen05 grouped GEMM, bf16x3, BM=256/BN=256/Kc=64, 3 smem stages,
// TMEM ping-pong (2 x 256 cols). grid (2, 74, 1), cluster (2,1,1), 288 threads:
//   wid 0-7 (256 thr): tile epilogues;  tid256: TMA producer;  tid257@rank0: MMA consumer.
// Epilogue of tile t-1 overlaps MMA of tile t.
template<int MODE>
__global__ __launch_bounds__(288) __cluster_dims__(2, 1, 1)
void gemm_tc2(const __grid_constant__ CUtensorMap mAh,
              const __grid_constant__ CUtensorMap mAl,
              const __grid_constant__ CUtensorMap mBh,
              const __grid_constant__ CUtensorMap mBl) {
#if HAS_TCGEN05
    constexpr int KDIM = MODE ? I_DIM : H_DIM;
    constexpr int NC   = KDIM / 64;
    constexpr int TPE  = MODE ? TPE2 : TPE1;
    constexpr int NTIL = MODE ? NTIL2 : NTIL1;

    const uint32_t rank = ctarank();
    const int tid = threadIdx.x;
    const int wid = tid >> 5, lane = tid & 31;

    extern __shared__ __align__(1024) char smem[];
    const uint32_t sb = smem_u32(smem);

    if (wid == 0) tcg_alloc2(sb + SM_TMEMPTR, 512);
    if (tid == 0) {
#pragma unroll
        for (int s = 0; s < NSTG; s++) {
            mbar_init(sb + SM_FILL + 8 * s, 1);
            mbar_init(sb + SM_DONE + 8 * s, 1);
        }
        mbar_init(sb + SM_TDONE, 1);     mbar_init(sb + SM_TDONE + 8, 1);
        mbar_init(sb + SM_EPI, 16);      mbar_init(sb + SM_EPI + 8, 16);
    }
    __syncthreads();
    uint32_t tm;
    asm volatile("ld.shared.b32 %0, [%1];" : "=r"(tm) : "r"(sb + SM_TMEMPTR));
    cluster_sync_();

    const int is_prod = (tid == 256);
    const int is_cons = (tid == 257 && rank == 0);
    const int is_epi  = (wid < 8);

    int cc = 0;                         // producer chunk counter
    int mc = 0;                         // consumer chunk counter
    int dp[NSTG] = {0, 0, 0};           // producer DONE parities
    int fq[NSTG] = {0, 0, 0};           // consumer FILL parities
    int tpp[2] = {0, 0};                // epilogue TDONE parities (per buffer)
    int epp[2] = {0, 0};                // consumer EPI parities (per buffer)
    int td = 0;                         // tiles processed (this cluster)
    int nidx = 0;

    for (int tl = 0; tl < NTIL; tl++) {
        const int e = tl / TPE, rr = tl % TPE;
        const int mpair = rr & 3, nblk = rr >> 2;
        const int count = g_cnt[e];
        if (mpair * 256 >= count) continue;
        if (nidx++ % NCLUS != (int)blockIdx.y) continue;
        const int pm0 = mpair * 256;
        const int bi = td & 1;
        const uint32_t dtm = tm + (uint32_t)bi * 256;

        const int arow0 = e * CAP + pm0 + (int)rank * 128;
        int brow0;
        if (MODE == 0) brow0 = e * N1 + ((int)rank ? I_DIM : 0) + nblk * 128;
        else           brow0 = e * H_DIM + nblk * 256 + (int)rank * 128;

        // ---- producer: issue TMA chunks ----
        if (is_prod) {
            for (int c = 0; c < NC; c++, cc++) {
                const int st = cc % NSTG;
                if (cc >= NSTG) { mbar_wait(sb + SM_DONE + 8 * st, dp[st]); dp[st] ^= 1; }
                const uint32_t bufb = sb + SM_BUF + st * STG_SZ;
                const uint32_t fill = sb + SM_FILL + 8 * st;
                const int k0 = c * 64;
                if (rank == 0) mbar_expect_tx(fill, CHUNK_TX);
                tma_cg2(bufb + OFF_AH, &mAh, k0, arow0, fill);
                tma_cg2(bufb + OFF_AL, &mAl, k0, arow0, fill);
                tma_cg2(bufb + OFF_BH, &mBh, k0, brow0, fill);
                tma_cg2(bufb + OFF_BL, &mBl, k0, brow0, fill);
            }
        }

        // ---- consumer: MMA chunks into buffer bi ----
        if (is_cons) {
            if (td >= 2) { mbar_wait(sb + SM_EPI + 8 * bi, epp[bi]); epp[bi] ^= 1; }
            for (int c = 0; c < NC; c++, mc++) {
                const int st = mc % NSTG;
                mbar_wait(sb + SM_FILL + 8 * st, fq[st]); fq[st] ^= 1;
                const uint32_t bufb = sb + SM_BUF + st * STG_SZ;
                const uint64_t ah = desc_k_sw128(bufb + OFF_AH);
                const uint64_t al = desc_k_sw128(bufb + OFF_AL);
                const uint64_t bh = desc_k_sw128(bufb + OFF_BH);
                const uint64_t bl = desc_k_sw128(bufb + OFF_BL);
#pragma unroll
                for (int s = 0; s < 4; s++) {
                    const uint64_t as = (uint64_t)s * 2;
                    const uint32_t en0 = (c > 0 || s > 0) ? 1u : 0u;
                    tcg_mma2(dtm, ah + as, bh + as, en0);
                    tcg_mma2(dtm, ah + as, bl + as, 1u);
                    tcg_mma2(dtm, al + as, bh + as, 1u);
                }
                tcg_commit_mc2(sb + SM_DONE + 8 * st, 0x3);
                if (c == NC - 1) tcg_commit_mc2(sb + SM_TDONE + 8 * bi, 0x3);
            }
        }

        // ---- epilogue warps: wait this tile's MMA, drain buffer bi ----
        if (is_epi) {
            mbar_wait(sb + SM_TDONE + 8 * bi, tpp[bi]); tpp[bi] ^= 1;
            tcg_fence_after();

            const int wq = wid & 3, wg = (wid >> 2) & 1;
            const int row = wq * 32 + lane;
            const int slot = pm0 + (int)rank * 128 + row;

            if (MODE == 0) {
                uint32_t rg[64], ru[64];
                ldtm32(rg,      dtm + wg * 64);
                ldtm32(rg + 32, dtm + wg * 64 + 32);
                ldtm32(ru,      dtm + 128 + wg * 64);
                ldtm32(ru + 32, dtm + 128 + wg * 64 + 32);
                tcg_wait_ld();
                const int ocol = nblk * 128 + wg * 64;
                unsigned short* oh = g_hh + ((size_t)e * CAP + slot) * I_DIM + ocol;
                unsigned short* ol = g_hl + ((size_t)e * CAP + slot) * I_DIM + ocol;
#pragma unroll
                for (int j = 0; j < 32; j++) {
                    float g0 = __uint_as_float(rg[2*j]),   u0 = __uint_as_float(ru[2*j]);
                    float g1 = __uint_as_float(rg[2*j+1]), u1 = __uint_as_float(ru[2*j+1]);
                    float h0 = (g0 / (1.f + __expf(-g0))) * u0;
                    float h1 = (g1 / (1.f + __expf(-g1))) * u1;
                    unsigned short a0, a1, b0, b1;
                    split_bf16(h0, a0, b0);
                    split_bf16(h1, a1, b1);
                    ((uint32_t*)oh)[j] = (uint32_t)a0 | ((uint32_t)a1 << 16);
                    ((uint32_t*)ol)[j] = (uint32_t)b0 | ((uint32_t)b1 << 16);
                }
            } else {
                const int ok = (slot < count);
                float wv = 0.f; int aid = 0;
                if (ok) { wv = g_wgt[e * CAP + slot]; aid = g_aid[e * CAP + slot]; }
                float* yp = g_y + (size_t)aid * H_DIM + nblk * 256 + wg * 128;
#pragma unroll
                for (int q = 0; q < 4; q++) {
                    uint32_t r[32];
                    ldtm32(r, dtm + wg * 128 + q * 32);
                    tcg_wait_ld();
                    if (ok) {
#pragma unroll
                        for (int i = 0; i < 8; i++) {
                            float4 v;
                            v.x = __uint_as_float(r[4*i+0]) * wv;
                            v.y = __uint_as_float(r[4*i+1]) * wv;
                            v.z = __uint_as_float(r[4*i+2]) * wv;
                            v.w = __uint_as_float(r[4*i+3]) * wv;
                            *(float4*)&yp[q * 32 + 4 * i] = v;
                        }
                    }
                }
            }
            tcg_fence_before();
            __syncwarp();
            if (lane == 0) mbar_arrive_rank0(sb + SM_EPI + 8 * bi);
        }
        td++;
    }

    __syncthreads();
    if (wid == 0) { tcg_relinq2(); tcg_dealloc2(tm, 512); }
    cluster_sync_();
#endif  // HAS_TCGEN05
}

// ---------------- combine (float4) ----------------
__global__ void combine_kernel(float* __restrict__ out) {
    const int idx = blockIdx.x * 256 + threadIdx.x;
    const int t = idx / (H_DIM / 4);
    const int c4 = idx % (H_DIM / 4);
    const float4* yb = (const float4*)(g_y + ((size_t)t * K_TOP) * H_DIM) + c4;
    float4 s = make_float4(0.f, 0.f, 0.f, 0.f);
#pragma unroll
    for (int k = 0; k < K_TOP; k++) {
        float4 v = yb[(size_t)k * (H_DIM / 4)];
        s.x += v.x; s.y += v.y; s.z += v.z; s.w += v.w;
    }
    ((float4*)out)[idx] = s;
}

// ---------------- host: tensormap construction via driver entry point ----------------
typedef CUresult (*PFN_tmEncode)(CUtensorMap*, CUtensorMapDataType, cuuint32_t, void*,
                                 const cuuint64_t*, const cuuint64_t*, const cuuint32_t*,
                                 const cuuint32_t*, CUtensorMapInterleave, CUtensorMapSwizzle,
                                 CUtensorMapL2promotion, CUtensorMapFloatOOBfill);

static PFN_tmEncode tm_encoder() {
    static PFN_tmEncode fn = nullptr;
    if (!fn) {
        void* p = nullptr;
        cudaDriverEntryPointQueryResult qr;
        cudaGetDriverEntryPoint("cuTensorMapEncodeTiled", &p, cudaEnableDefault, &qr);
        fn = (PFN_tmEncode)p;
    }
    return fn;
}

static void make_map(CUtensorMap* m, void* base, unsigned long long rows,
                     unsigned long long cols, unsigned boxrows) {
    cuuint64_t dims[3] = {cols, rows, 1};
    cuuint64_t strides[2] = {cols * 2, cols * 2 * rows};
    cuuint32_t box[3] = {64, boxrows, 1};
    cuuint32_t es[3] = {1, 1, 1};
    tm_encoder()(m, CU_TENSOR_MAP_DATA_TYPE_BFLOAT16, 3, base, dims, strides, box, es,
                 CU_TENSOR_MAP_INTERLEAVE_NONE, CU_TENSOR_MAP_SWIZZLE_128B,
                 CU_TENSOR_MAP_L2_PROMOTION_L2_128B, CU_TENSOR_MAP_FLOAT_OOB_FILL_NONE);
}

// ---------------- launch ----------------
extern "C" void kernel_launch(void* const* d_in, const int* in_sizes, int n_in,
                              void* d_out, int out_size) {
    const float* x  = (const float*)d_in[0];
    const float* gw = (const float*)d_in[1];
    const float* gb = (const float*)d_in[2];
    const float* w1 = (const float*)d_in[3];
    const float* w2 = (const float*)d_in[4];
    float* out = (float*)d_out;

    cudaFuncSetAttribute(gemm_tc2<0>, cudaFuncAttributeMaxDynamicSharedMemorySize, SMEM_TC);
    cudaFuncSetAttribute(gemm_tc2<1>, cudaFuncAttributeMaxDynamicSharedMemorySize, SMEM_TC);

    void *gah, *gal, *hh, *hl, *w1h, *w1l, *w2h, *w2l;
    cudaGetSymbolAddress(&gah, g_gah);
    cudaGetSymbolAddress(&gal, g_gal);
    cudaGetSymbolAddress(&hh,  g_hh);
    cudaGetSymbolAddress(&hl,  g_hl);
    cudaGetSymbolAddress(&w1h, g_w1h);
    cudaGetSymbolAddress(&w1l, g_w1l);
    cudaGetSymbolAddress(&w2h, g_w2h);
    cudaGetSymbolAddress(&w2l, g_w2l);

    CUtensorMap m1Ah, m1Al, m1Bh, m1Bl, m2Ah, m2Al, m2Bh, m2Bl;
    make_map(&m1Ah, gah, (unsigned long long)E_NUM * CAP, H_DIM, 128);
    make_map(&m1Al, gal, (unsigned long long)E_NUM * CAP, H_DIM, 128);
    make_map(&m1Bh, w1h, (unsigned long long)E_NUM * N1, H_DIM, 128);
    make_map(&m1Bl, w1l, (unsigned long long)E_NUM * N1, H_DIM, 128);
    make_map(&m2Ah, hh,  (unsigned long long)E_NUM * CAP, I_DIM, 128);
    make_map(&m2Al, hl,  (unsigned long long)E_NUM * CAP, I_DIM, 128);
    make_map(&m2Bh, w2h, (unsigned long long)E_NUM * H_DIM, I_DIM, 128);
    make_map(&m2Bl, w2l, (unsigned long long)E_NUM * H_DIM, I_DIM, 128);

    // conv1 also preps router state (gate_wT transpose + cnt reset)
    conv_kernel<H_DIM, N1><<<dim3(H_DIM / 64, N1 / 64, E_NUM), 256>>>(
        w1, (unsigned short*)w1h, (unsigned short*)w1l, gw);                            // 0
    router_kernel<<<T_TOK, 256>>>(x, gb);                                               // 1
    pregather_kernel<<<E_NUM * CAP, 256>>>(x);                                          // 2
    gemm_tc2<0><<<dim3(2, NCLUS, 1), 288, SMEM_TC>>>(m1Ah, m1Al, m1Bh, m1Bl);           // 3 (profiled)
    conv_kernel<I_DIM, H_DIM><<<dim3(I_DIM / 64, H_DIM / 64, E_NUM), 256>>>(
        w2, (unsigned short*)w2h, (unsigned short*)w2l, nullptr);                       // 4
    gemm_tc2<1><<<dim3(2, NCLUS, 1), 288, SMEM_TC>>>(m2Ah, m2Al, m2Bh, m2Bl);           // 5
    combine_kernel<<<(T_TOK * H_DIM / 4) / 256, 256>>>(out);                            // 6
}

// round 16
// speedup vs baseline: 1.1471x; 1.1471x over previous
#include <cuda_runtime.h>
#include <cuda.h>
#include <cuda_bf16.h>
#include <math.h>
#include <stdint.h>

#define T_TOK 2048
#define H_DIM 2048
#define I_DIM 768
#define E_NUM 32
#define K_TOP 8
#define CAP   1024
#define A_TOTAL (T_TOK * K_TOP)
#define N1 (2 * I_DIM)          // 1536

#define TPE1 12                 // gemm1: 4 mpair x 3 nblk (256 h cols per tile)
#define TPE2 16                 // gemm2: 4 mpair x 4 nblk (512 H cols per tile)
#define NTIL1 (E_NUM * TPE1)    // 384
#define NTIL2 (E_NUM * TPE2)    // 512
#define NCLUS 74
#define NSTG  2

#if defined(__CUDA_ARCH__)
#  if defined(__CUDA_ARCH_FEAT_SM103_ALL) || defined(__CUDA_ARCH_FEAT_SM100_ALL) || \
      (defined(__CUDA_ARCH_SPECIFIC__) && (__CUDA_ARCH_SPECIFIC__ == 1030 || __CUDA_ARCH_SPECIFIC__ == 1000))
#    define HAS_TCGEN05 1
#  else
#    define HAS_TCGEN05 0
#  endif
#else
#  define HAS_TCGEN05 0
#endif

// ---------------- device scratch ----------------
__device__ float g_gate_wT[E_NUM * H_DIM];
__device__ int   g_cnt[E_NUM];
__device__ int   g_tok[E_NUM * CAP];
__device__ int   g_aid[E_NUM * CAP];
__device__ float g_wgt[E_NUM * CAP];
__device__ unsigned short g_gah[(size_t)E_NUM * CAP * H_DIM];  // pregathered A hi
__device__ unsigned short g_gal[(size_t)E_NUM * CAP * H_DIM];  // pregathered A lo
__device__ unsigned short g_hh[(size_t)E_NUM * CAP * I_DIM];
__device__ unsigned short g_hl[(size_t)E_NUM * CAP * I_DIM];
__device__ float g_y[(size_t)A_TOTAL * H_DIM];
__device__ unsigned short g_w1h[(size_t)E_NUM * N1 * H_DIM];
__device__ unsigned short g_w1l[(size_t)E_NUM * N1 * H_DIM];
__device__ unsigned short g_w2h[(size_t)E_NUM * H_DIM * I_DIM];
__device__ unsigned short g_w2l[(size_t)E_NUM * H_DIM * I_DIM];

// ---------------- helpers ----------------
__device__ __forceinline__ void split_bf16(float x, unsigned short& h, unsigned short& l) {
    __nv_bfloat16 bh = __float2bfloat16_rn(x);
    h = *reinterpret_cast<unsigned short*>(&bh);
    float r = x - __bfloat162float(bh);
    __nv_bfloat16 bl = __float2bfloat16_rn(r);
    l = *reinterpret_cast<unsigned short*>(&bl);
}
__device__ __forceinline__ uint32_t smem_u32(const void* p) {
    return (uint32_t)__cvta_generic_to_shared(p);
}

// ---------------- weight conversion (64-row tiles); w1 pass also preps router state ----------------
template<int KD, int ND>
__global__ __launch_bounds__(256) void conv_kernel(const float* __restrict__ W,
                                                   unsigned short* __restrict__ Wh,
                                                   unsigned short* __restrict__ Wl,
                                                   const float* __restrict__ gate_w) {
    const int e = blockIdx.z;
    const int k0 = blockIdx.x * 64;
    const int n0 = blockIdx.y * 64;
    __shared__ float ts[64][65];
    const int tid = threadIdx.x;

    if (gate_w && blockIdx.x == 0 && blockIdx.y == 0) {
        for (int h = tid; h < H_DIM; h += 256)
            g_gate_wT[e * H_DIM + h] = gate_w[h * E_NUM + e];
        if (e == 0 && tid < E_NUM) g_cnt[tid] = 0;
    }

    const int lr = tid >> 4, lc = (tid & 15) * 4;
    const float* src = W + (size_t)e * KD * ND + (size_t)k0 * ND + n0;
#pragma unroll
    for (int it = 0; it < 4; it++) {
        const int row = lr + it * 16;
        float4 v = *(const float4*)(src + (size_t)row * ND + lc);
        ts[row][lc + 0] = v.x; ts[row][lc + 1] = v.y;
        ts[row][lc + 2] = v.z; ts[row][lc + 3] = v.w;
    }
    __syncthreads();

    const int n = tid >> 2, ks = (tid & 3) * 16;
    uint32_t hh[8], ll[8];
#pragma unroll
    for (int q = 0; q < 8; q++) {
        unsigned short h0, h1, l0, l1;
        split_bf16(ts[ks + 2 * q][n],     h0, l0);
        split_bf16(ts[ks + 2 * q + 1][n], h1, l1);
        hh[q] = (uint32_t)h0 | ((uint32_t)h1 << 16);
        ll[q] = (uint32_t)l0 | ((uint32_t)l1 << 16);
    }
    const size_t doff = ((size_t)e * ND + n0 + n) * KD + k0 + ks;
    *(uint4*)(Wh + doff)     = make_uint4(hh[0], hh[1], hh[2], hh[3]);
    *(uint4*)(Wh + doff + 8) = make_uint4(hh[4], hh[5], hh[6], hh[7]);
    *(uint4*)(Wl + doff)     = make_uint4(ll[0], ll[1], ll[2], ll[3]);
    *(uint4*)(Wl + doff + 8) = make_uint4(ll[4], ll[5], ll[6], ll[7]);
}

// ---------------- router ----------------
__global__ __launch_bounds__(256) void router_kernel(const float* __restrict__ x,
                                                     const float* __restrict__ gate_b) {
    __shared__ float xs[H_DIM];
    __shared__ float lg[E_NUM];
    const int t = blockIdx.x;
    const int tid = threadIdx.x;

    const float4* xr = (const float4*)(x + (size_t)t * H_DIM);
    for (int i = tid; i < H_DIM / 4; i += 256) ((float4*)xs)[i] = xr[i];
    __syncthreads();

    const int w = tid >> 5, lane = tid & 31;
#pragma unroll
    for (int ee = 0; ee < 4; ee++) {
        const int e = (w << 2) + ee;
        const float* gw = g_gate_wT + (size_t)e * H_DIM;
        float s = 0.f;
        for (int h = lane; h < H_DIM; h += 32) s += xs[h] * gw[h];
#pragma unroll
        for (int off = 16; off; off >>= 1) s += __shfl_xor_sync(0xffffffffu, s, off);
        if (lane == 0) lg[e] = s + gate_b[e];
    }
    __syncthreads();

    if (tid == 0) {
        float mx = lg[0];
#pragma unroll
        for (int e = 1; e < E_NUM; e++) mx = fmaxf(mx, lg[e]);
        float p[E_NUM];
#pragma unroll
        for (int e = 0; e < E_NUM; e++) p[e] = __expf(lg[e] - mx);
        float vals[K_TOP]; int sel[K_TOP]; float vsum = 0.f;
#pragma unroll
        for (int k = 0; k < K_TOP; k++) {
            int bj = 0; float bv = p[0];
            for (int e = 1; e < E_NUM; e++) if (p[e] > bv) { bv = p[e]; bj = e; }
            sel[k] = bj; vals[k] = bv; vsum += bv; p[bj] = -1.f;
        }
        const float inv = 1.f / vsum;
#pragma unroll
        for (int k = 0; k < K_TOP; k++) {
            const int e = sel[k];
            int slot = atomicAdd(&g_cnt[e], 1);
            if (slot < CAP) {
                g_tok[e * CAP + slot] = t;
                g_aid[e * CAP + slot] = (t << 3) + k;
                g_wgt[e * CAP + slot] = vals[k] * inv;
            }
        }
    }
}

// ---------------- pregather: x rows -> split bf16 hi/lo [E*CAP][H] ----------------
__global__ __launch_bounds__(256) void pregather_kernel(const float* __restrict__ x) {
    const int bid = blockIdx.x;                // e*CAP + slot
    const int e = bid >> 10, slot = bid & (CAP - 1);
    const int count = g_cnt[e];
    int s = slot; if (s >= count) s = (count > 0) ? count - 1 : 0;
    const int tok = g_tok[e * CAP + s];
    const int c0 = threadIdx.x * 8;
    const float* src = x + (size_t)tok * H_DIM + c0;
    float4 v0 = *(const float4*)src;
    float4 v1 = *(const float4*)(src + 4);
    float vv[8] = {v0.x, v0.y, v0.z, v0.w, v1.x, v1.y, v1.z, v1.w};
    uint32_t hh[4], ll[4];
#pragma unroll
    for (int q = 0; q < 4; q++) {
        unsigned short h0, h1, l0, l1;
        split_bf16(vv[2 * q],     h0, l0);
        split_bf16(vv[2 * q + 1], h1, l1);
        hh[q] = (uint32_t)h0 | ((uint32_t)h1 << 16);
        ll[q] = (uint32_t)l0 | ((uint32_t)l1 << 16);
    }
    const size_t o = (size_t)bid * H_DIM + c0;
    *(uint4*)(g_gah + o) = make_uint4(hh[0], hh[1], hh[2], hh[3]);
    *(uint4*)(g_gal + o) = make_uint4(ll[0], ll[1], ll[2], ll[3]);
}

// ---------------- smem arena: 2 stages x 96KB ----------------
#define SM_TMEMPTR 0
#define SM_FILL    16          // FILL[s]@16+8s (count=1 + expect_tx, on rank0)
#define SM_DONE    32          // DONE[s]@32+8s (count=1, commit multicast)
#define SM_TDONE   48
#define SM_EPI     56          // count=16 (8 warps x 2 CTAs), on rank0
#define SM_BUF     1024
#define OFF_AH     0           // 16KB (128 rows x 128B)
#define OFF_AL     16384
#define OFF_BH     32768       // 32KB (256 local rows x 128B)
#define OFF_BL     65536
#define STG_SZ     98304
#define SMEM_TC    (SM_BUF + NSTG * STG_SZ)   // 197632
#define CHUNK_TX   196608      // (16+16+32+32)KB x 2 CTAs

#if HAS_TCGEN05
__device__ __forceinline__ uint32_t ctarank() {
    uint32_t r;
    asm("mov.u32 %0, %%cluster_ctarank;" : "=r"(r));
    return r;
}
__device__ __forceinline__ uint64_t desc_k_sw128(uint32_t addr) {
    return ((uint64_t)(addr >> 4) & 0x3FFF) | (1ull << 16) | (64ull << 32)
         | (1ull << 46) | (2ull << 61);
}
// idesc kind::f16 cg2: dtype=F32, atype=BF16, btype=BF16, N=256, M=256 (validated)
#define MMA_IDESC2 ((1u << 4) | (1u << 7) | (1u << 10) | ((256u / 8) << 17) | ((256u / 16) << 24))

__device__ __forceinline__ void tcg_mma2(uint32_t d, uint64_t a, uint64_t b, uint32_t en) {
    asm volatile(
        "{\n\t.reg .pred p;\n\tsetp.ne.u32 p, %4, 0;\n\t"
        "tcgen05.mma.cta_group::2.kind::f16 [%0], %1, %2, %3, "
        "{%5, %5, %5, %5, %5, %5, %5, %5}, p;\n\t}"
        :: "r"(d), "l"(a), "l"(b), "r"(MMA_IDESC2), "r"(en), "r"(0u) : "memory");
}
__device__ __forceinline__ void tcg_commit_mc2(uint32_t mbar, uint16_t mask) {
    asm volatile(
        "tcgen05.commit.cta_group::2.mbarrier::arrive::one.shared::cluster.multicast::cluster.b64 [%0], %1;"
        :: "r"(mbar), "h"(mask) : "memory");
}
__device__ __forceinline__ void tcg_alloc2(uint32_t smem_res, uint32_t ncols) {
    asm volatile("tcgen05.alloc.cta_group::2.sync.aligned.shared::cta.b32 [%0], %1;"
                 :: "r"(smem_res), "r"(ncols) : "memory");
}
__device__ __forceinline__ void tcg_dealloc2(uint32_t tmem, uint32_t ncols) {
    asm volatile("tcgen05.dealloc.cta_group::2.sync.aligned.b32 %0, %1;" :: "r"(tmem), "r"(ncols));
}
__device__ __forceinline__ void tcg_relinq2() {
    asm volatile("tcgen05.relinquish_alloc_permit.cta_group::2.sync.aligned;");
}
__device__ __forceinline__ void mbar_init(uint32_t mbar, uint32_t cnt) {
    asm volatile("mbarrier.init.shared.b64 [%0], %1;" :: "r"(mbar), "r"(cnt) : "memory");
}
__device__ __forceinline__ void mbar_expect_tx(uint32_t mbar, uint32_t bytes) {
    asm volatile("mbarrier.arrive.expect_tx.shared.b64 _, [%0], %1;"
                 :: "r"(mbar), "r"(bytes) : "memory");
}
__device__ __forceinline__ void mbar_arrive_rank0(uint32_t addr) {
    asm volatile(
        "{\n\t.reg .b32 r;\n\t"
        "mapa.shared::cluster.u32 r, %0, 0;\n\t"
        "mbarrier.arrive.shared::cluster.b64 _, [r];\n\t}"
        :: "r"(addr) : "memory");
}
__device__ __forceinline__ void mbar_wait(uint32_t mbar, uint32_t parity) {
    uint32_t done;
    asm volatile(
        "{\n\t.reg .pred p;\n\t"
        "mbarrier.try_wait.parity.acquire.cta.shared::cta.b64 p, [%1], %2;\n\t"
        "selp.b32 %0, 1, 0, p;\n\t}"
        : "=r"(done) : "r"(mbar), "r"(parity) : "memory");
    if (!done) {
        asm volatile(
            "{\n\t.reg .pred P1;\n\t"
            "WAIT_LOOP_%=:\n\t"
            "mbarrier.try_wait.parity.acquire.cta.shared::cta.b64 P1, [%0], %1, 0x989680;\n\t"
            "@P1 bra.uni WAIT_DONE_%=;\n\t"
            "bra.uni WAIT_LOOP_%=;\n\t"
            "WAIT_DONE_%=:\n\t}"
            :: "r"(mbar), "r"(parity) : "memory");
    }
}
// cg2 TMA: both CTAs issue; complete_tx credited to rank0's barrier (bit 24 cleared)
__device__ __forceinline__ void tma_cg2(uint32_t dst, const CUtensorMap* map,
                                        int x, int y, uint32_t bar) {
    asm volatile(
        "{\n\t.reg .b32 lb;\n\tand.b32 lb, %5, 0xFEFFFFFF;\n\t"
        "cp.async.bulk.tensor.3d.cta_group::2.shared::cluster.global.tile.mbarrier::complete_tx::bytes "
        "[%0], [%1, {%2, %3, %4}], [lb];\n\t}"
        :: "r"(dst), "l"(map), "r"(x), "r"(y), "r"(0), "r"(bar) : "memory");
}
__device__ __forceinline__ void tcg_fence_after() {
    asm volatile("tcgen05.fence::after_thread_sync;" ::: "memory");
}
__device__ __forceinline__ void tcg_fence_before() {
    asm volatile("tcgen05.fence::before_thread_sync;" ::: "memory");
}
__device__ __forceinline__ void tcg_wait_ld() {
    asm volatile("tcgen05.wait::ld.sync.aligned;" ::: "memory");
}
__device__ __forceinline__ void cluster_sync_() {
    asm volatile("barrier.cluster.arrive.aligned;" ::: "memory");
    asm volatile("barrier.cluster.wait.aligned;" ::: "memory");
}
__device__ __forceinline__ void ldtm32(uint32_t* r, uint32_t addr) {
    asm volatile(
        "tcgen05.ld.sync.aligned.32x32b.x32.b32 "
        "{%0, %1, %2, %3, %4, %5, %6, %7, "
        " %8, %9, %10, %11, %12, %13, %14, %15, "
        " %16, %17, %18, %19, %20, %21, %22, %23, "
        " %24, %25, %26, %27, %28, %29, %30, %31}, [%32];"
        : "=r"(r[0]),  "=r"(r[1]),  "=r"(r[2]),  "=r"(r[3]),
          "=r"(r[4]),  "=r"(r[5]),  "=r"(r[6]),  "=r"(r[7]),
          "=r"(r[8]),  "=r"(r[9]),  "=r"(r[10]), "=r"(r[11]),
          "=r"(r[12]), "=r"(r[13]), "=r"(r[14]), "=r"(r[15]),
          "=r"(r[16]), "=r"(r[17]), "=r"(r[18]), "=r"(r[19]),
          "=r"(r[20]), "=r"(r[21]), "=r"(r[22]), "=r"(r[23]),
          "=r"(r[24]), "=r"(r[25]), "=r"(r[26]), "=r"(r[27]),
          "=r"(r[28]), "=r"(r[29]), "=r"(r[30]), "=r"(r[31])
        : "r"(addr));
}
#endif  // HAS_TCGEN05

// Persistent 2-CTA TMA+tcgen05 grouped GEMM, bf16x3, BM=256/BN=512/Kc=64.
// grid (2, 74, 1), cluster (2,1,1), 256 threads. tid32 = TMA producer (both ranks);
// tid0@rank0 = MMA consumer. 8 warps do the tile epilogue.
template<int MODE>
__global__ __launch_bounds__(256) __cluster_dims__(2, 1, 1)
void gemm_tc2(const __grid_constant__ CUtensorMap mAh,
              const __grid_constant__ CUtensorMap mAl,
              const __grid_constant__ CUtensorMap mBh,
              const __grid_constant__ CUtensorMap mBl) {
#if HAS_TCGEN05
    constexpr int KDIM = MODE ? I_DIM : H_DIM;
    constexpr int NC   = KDIM / 64;
    constexpr int TPE  = MODE ? TPE2 : TPE1;
    constexpr int NTIL = MODE ? NTIL2 : NTIL1;

    const uint32_t rank = ctarank();
    const int tid = threadIdx.x;
    const int wid = tid >> 5, lane = tid & 31;

    extern __shared__ __align__(1024) char smem[];
    const uint32_t sb = smem_u32(smem);

    if (wid == 0) tcg_alloc2(sb + SM_TMEMPTR, 512);
    if (tid == 0) {
#pragma unroll
        for (int s = 0; s < NSTG; s++) {
            mbar_init(sb + SM_FILL + 8 * s, 1);
            mbar_init(sb + SM_DONE + 8 * s, 1);
        }
        mbar_init(sb + SM_TDONE, 1);
        mbar_init(sb + SM_EPI, 16);
    }
    __syncthreads();
    uint32_t tm;
    asm volatile("ld.shared.b32 %0, [%1];" : "=r"(tm) : "r"(sb + SM_TMEMPTR));
    cluster_sync_();

    const int is_prod = (tid == 32);
    const int is_cons = (tid == 0 && rank == 0);

    int cc = 0;                     // producer chunk counter
    int mc = 0;                     // consumer chunk counter
    int dp[NSTG] = {0, 0};          // producer DONE parities
    int fq[NSTG] = {0, 0};          // consumer FILL parities
    int tp = 0;                     // TDONE parity (all threads)
    int ep = 0;                     // EPI parity (consumer)
    int tiles_done = 0;
    int nidx = 0;

    for (int tl = 0; tl < NTIL; tl++) {
        const int e = tl / TPE, rr = tl % TPE;
        const int mpair = rr & 3, nblk = rr >> 2;
        const int count = g_cnt[e];
        if (mpair * 256 >= count) continue;
        if (nidx++ % NCLUS != (int)blockIdx.y) continue;
        const int pm0 = mpair * 256;

        const int arow0 = e * CAP + pm0 + (int)rank * 128;
        int brow0;
        if (MODE == 0) brow0 = e * N1 + ((int)rank ? I_DIM : 0) + nblk * 256;
        else           brow0 = e * H_DIM + nblk * 512 + (int)rank * 256;

        // ---- producer: issue TMA chunks ----
        if (is_prod) {
            for (int c = 0; c < NC; c++, cc++) {
                const int st = cc & 1;
                if (cc >= NSTG) { mbar_wait(sb + SM_DONE + 8 * st, dp[st]); dp[st] ^= 1; }
                const uint32_t bufb = sb + SM_BUF + st * STG_SZ;
                const uint32_t fill = sb + SM_FILL + 8 * st;
                const int k0 = c * 64;
                if (rank == 0) mbar_expect_tx(fill, CHUNK_TX);
                tma_cg2(bufb + OFF_AH, &mAh, k0, arow0, fill);
                tma_cg2(bufb + OFF_AL, &mAl, k0, arow0, fill);
                tma_cg2(bufb + OFF_BH, &mBh, k0, brow0, fill);
                tma_cg2(bufb + OFF_BL, &mBl, k0, brow0, fill);
            }
        }

        // ---- consumer: MMA chunks ----
        if (is_cons) {
            for (int c = 0; c < NC; c++, mc++) {
                const int st = mc & 1;
                mbar_wait(sb + SM_FILL + 8 * st, fq[st]); fq[st] ^= 1;
                if (c == 0 && tiles_done > 0) { mbar_wait(sb + SM_EPI, ep); ep ^= 1; }
                const uint32_t bufb = sb + SM_BUF + st * STG_SZ;
                const uint64_t ah = desc_k_sw128(bufb + OFF_AH);
                const uint64_t al = desc_k_sw128(bufb + OFF_AL);
#pragma unroll
                for (int s = 0; s < 4; s++) {
                    const uint64_t as = (uint64_t)s * 2;
#pragma unroll
                    for (int nh = 0; nh < 2; nh++) {
                        const uint64_t bh = desc_k_sw128(bufb + OFF_BH + nh * 16384) + as;
                        const uint64_t bl = desc_k_sw128(bufb + OFF_BL + nh * 16384) + as;
                        const uint32_t d = tm + nh * 256;
                        const uint32_t en0 = (c > 0 || s > 0) ? 1u : 0u;
                        tcg_mma2(d, ah + as, bh, en0);
                        tcg_mma2(d, ah + as, bl, 1u);
                        tcg_mma2(d, al + as, bh, 1u);
                    }
                }
                tcg_commit_mc2(sb + SM_DONE + 8 * st, 0x3);
                if (c == NC - 1) tcg_commit_mc2(sb + SM_TDONE, 0x3);
            }
        }

        // ---- all threads: wait tile completion, epilogue ----
        mbar_wait(sb + SM_TDONE, tp); tp ^= 1;
        __syncwarp();
        tcg_fence_after();

        const int wq = wid & 3, wg = (wid >> 2) & 1;
        const int row = wq * 32 + lane;
        const int slot = pm0 + (int)rank * 128 + row;

        if (MODE == 0) {
            // D: gate(X) at col wg*256+lr, up(X) at wg*256+128+lr; X = nblk*256+wg*128+lr
            unsigned short* oh = g_hh + ((size_t)e * CAP + slot) * I_DIM + nblk * 256 + wg * 128;
            unsigned short* ol = g_hl + ((size_t)e * CAP + slot) * I_DIM + nblk * 256 + wg * 128;
#pragma unroll
            for (int q = 0; q < 4; q++) {
                uint32_t rg[32], ru[32];
                ldtm32(rg, tm + wg * 256 + q * 32);
                ldtm32(ru, tm + wg * 256 + 128 + q * 32);
                tcg_wait_ld();
#pragma unroll
                for (int j = 0; j < 16; j++) {
                    float g0 = __uint_as_float(rg[2*j]),   u0 = __uint_as_float(ru[2*j]);
                    float g1 = __uint_as_float(rg[2*j+1]), u1 = __uint_as_float(ru[2*j+1]);
                    float h0 = (g0 / (1.f + __expf(-g0))) * u0;
                    float h1 = (g1 / (1.f + __expf(-g1))) * u1;
                    unsigned short a0, a1, b0, b1;
                    split_bf16(h0, a0, b0);
                    split_bf16(h1, a1, b1);
                    ((uint32_t*)(oh + q * 32))[j] = (uint32_t)a0 | ((uint32_t)a1 << 16);
                    ((uint32_t*)(ol + q * 32))[j] = (uint32_t)b0 | ((uint32_t)b1 << 16);
                }
            }
        } else {
            const int ok = (slot < count);
            float wv = 0.f; int aid = 0;
            if (ok) { wv = g_wgt[e * CAP + slot]; aid = g_aid[e * CAP + slot]; }
#pragma unroll
            for (int hb = 0; hb < 2; hb++) {
                const int d0 = wg * 256 + hb * 128;
                float* yp = g_y + (size_t)aid * H_DIM + nblk * 512 + hb * 256 + wg * 128;
#pragma unroll
                for (int q = 0; q < 4; q++) {
                    uint32_t r[32];
                    ldtm32(r, tm + d0 + q * 32);
                    tcg_wait_ld();
                    if (ok) {
#pragma unroll
                        for (int i = 0; i < 8; i++) {
                            float4 v;
                            v.x = __uint_as_float(r[4*i+0]) * wv;
                            v.y = __uint_as_float(r[4*i+1]) * wv;
                            v.z = __uint_as_float(r[4*i+2]) * wv;
                            v.w = __uint_as_float(r[4*i+3]) * wv;
                            *(float4*)&yp[q * 32 + 4 * i] = v;
                        }
                    }
                }
            }
        }
        tcg_fence_before();
        __syncwarp();
        if (lane == 0) mbar_arrive_rank0(sb + SM_EPI);
        tiles_done++;
    }

    __syncthreads();
    if (wid == 0) { tcg_relinq2(); tcg_dealloc2(tm, 512); }
    cluster_sync_();
#endif  // HAS_TCGEN05
}

// ---------------- combine (float4) ----------------
__global__ void combine_kernel(float* __restrict__ out) {
    const int idx = blockIdx.x * 256 + threadIdx.x;
    const int t = idx / (H_DIM / 4);
    const int c4 = idx % (H_DIM / 4);
    const float4* yb = (const float4*)(g_y + ((size_t)t * K_TOP) * H_DIM) + c4;
    float4 s = make_float4(0.f, 0.f, 0.f, 0.f);
#pragma unroll
    for (int k = 0; k < K_TOP; k++) {
        float4 v = yb[(size_t)k * (H_DIM / 4)];
        s.x += v.x; s.y += v.y; s.z += v.z; s.w += v.w;
    }
    ((float4*)out)[idx] = s;
}

// ---------------- host: tensormap construction via driver entry point ----------------
typedef CUresult (*PFN_tmEncode)(CUtensorMap*, CUtensorMapDataType, cuuint32_t, void*,
                                 const cuuint64_t*, const cuuint64_t*, const cuuint32_t*,
                                 const cuuint32_t*, CUtensorMapInterleave, CUtensorMapSwizzle,
                                 CUtensorMapL2promotion, CUtensorMapFloatOOBfill);

static PFN_tmEncode tm_encoder() {
    static PFN_tmEncode fn = nullptr;
    if (!fn) {
        void* p = nullptr;
        cudaDriverEntryPointQueryResult qr;
        cudaGetDriverEntryPoint("cuTensorMapEncodeTiled", &p, cudaEnableDefault, &qr);
        fn = (PFN_tmEncode)p;
    }
    return fn;
}

static void make_map(CUtensorMap* m, void* base, unsigned long long rows,
                     unsigned long long cols, unsigned boxrows) {
    cuuint64_t dims[3] = {cols, rows, 1};
    cuuint64_t strides[2] = {cols * 2, cols * 2 * rows};
    cuuint32_t box[3] = {64, boxrows, 1};
    cuuint32_t es[3] = {1, 1, 1};
    tm_encoder()(m, CU_TENSOR_MAP_DATA_TYPE_BFLOAT16, 3, base, dims, strides, box, es,
                 CU_TENSOR_MAP_INTERLEAVE_NONE, CU_TENSOR_MAP_SWIZZLE_128B,
                 CU_TENSOR_MAP_L2_PROMOTION_L2_256B, CU_TENSOR_MAP_FLOAT_OOB_FILL_NONE);
}

// ---------------- launch ----------------
extern "C" void kernel_launch(void* const* d_in, const int* in_sizes, int n_in,
                              void* d_out, int out_size) {
    const float* x  = (const float*)d_in[0];
    const float* gw = (const float*)d_in[1];
    const float* gb = (const float*)d_in[2];
    const float* w1 = (const float*)d_in[3];
    const float* w2 = (const float*)d_in[4];
    float* out = (float*)d_out;

    cudaFuncSetAttribute(gemm_tc2<0>, cudaFuncAttributeMaxDynamicSharedMemorySize, SMEM_TC);
    cudaFuncSetAttribute(gemm_tc2<1>, cudaFuncAttributeMaxDynamicSharedMemorySize, SMEM_TC);

    void *gah, *gal, *hh, *hl, *w1h, *w1l, *w2h, *w2l;
    cudaGetSymbolAddress(&gah, g_gah);
    cudaGetSymbolAddress(&gal, g_gal);
    cudaGetSymbolAddress(&hh,  g_hh);
    cudaGetSymbolAddress(&hl,  g_hl);
    cudaGetSymbolAddress(&w1h, g_w1h);
    cudaGetSymbolAddress(&w1l, g_w1l);
    cudaGetSymbolAddress(&w2h, g_w2h);
    cudaGetSymbolAddress(&w2l, g_w2l);

    CUtensorMap m1Ah, m1Al, m1Bh, m1Bl, m2Ah, m2Al, m2Bh, m2Bl;
    make_map(&m1Ah, gah, (unsigned long long)E_NUM * CAP, H_DIM, 128);
    make_map(&m1Al, gal, (unsigned long long)E_NUM * CAP, H_DIM, 128);
    make_map(&m1Bh, w1h, (unsigned long long)E_NUM * N1, H_DIM, 256);
    make_map(&m1Bl, w1l, (unsigned long long)E_NUM * N1, H_DIM, 256);
    make_map(&m2Ah, hh,  (unsigned long long)E_NUM * CAP, I_DIM, 128);
    make_map(&m2Al, hl,  (unsigned long long)E_NUM * CAP, I_DIM, 128);
    make_map(&m2Bh, w2h, (unsigned long long)E_NUM * H_DIM, I_DIM, 256);
    make_map(&m2Bl, w2l, (unsigned long long)E_NUM * H_DIM, I_DIM, 256);

    // conv1 also preps router state (gate_wT transpose + cnt reset)
    conv_kernel<H_DIM, N1><<<dim3(H_DIM / 64, N1 / 64, E_NUM), 256>>>(
        w1, (unsigned short*)w1h, (unsigned short*)w1l, gw);                            // 0
    router_kernel<<<T_TOK, 256>>>(x, gb);                                               // 1
    pregather_kernel<<<E_NUM * CAP, 256>>>(x);                                          // 2
    gemm_tc2<0><<<dim3(2, NCLUS, 1), 256, SMEM_TC>>>(m1Ah, m1Al, m1Bh, m1Bl);           // 3 (profiled)
    conv_kernel<I_DIM, H_DIM><<<dim3(I_DIM / 64, H_DIM / 64, E_NUM), 256>>>(
        w2, (unsigned short*)w2h, (unsigned short*)w2l, nullptr);                       // 4
    gemm_tc2<1><<<dim3(2, NCLUS, 1), 256, SMEM_TC>>>(m2Ah, m2Al, m2Bh, m2Bl);           // 5
    combine_kernel<<<(T_TOK * H_DIM / 4) / 256, 256>>>(out);                            // 6
}